// round 12
// baseline (speedup 1.0000x reference)
#include <cuda_runtime.h>
#include <cuda_fp16.h>
#include <cuda_bf16.h>
#include <cstdint>

#define MAX_TOTAL 66560
#define MAX_B     2048
#define W_TOTAL   ((384 + 128) * 128)
#define W_WORDS   (W_TOTAL / 2)

__device__ float    g_ctx[(size_t)MAX_TOTAL * 128];
__device__ int      g_off[MAX_B];
__device__ int      g_order[MAX_B];
__device__ uint32_t g_whP[W_WORDS];                    // packed fp16x2 hi
__device__ uint32_t g_wlP[W_WORDS];                    // packed fp16x2 lo
__device__ uint32_t g_qP[(size_t)MAX_TOTAL * 64];      // Q/4 fp16x2, perm k
__device__ uint32_t g_kP[(size_t)MAX_TOTAL * 64];      // K fp16x2, perm k
__device__ float    g_vF[(size_t)MAX_TOTAL * 128];     // V fp32

__device__ __forceinline__ uint32_t packh(float a, float b) {
    uint32_t r;
    asm("cvt.rn.f16x2.f32 %0, %1, %2;" : "=r"(r) : "f"(b), "f"(a));
    return r;   // lo = a, hi = b
}
__device__ __forceinline__ uint32_t packbf(float a, float b) {
    uint32_t r;
    asm("cvt.rn.bf16x2.f32 %0, %1, %2;" : "=r"(r) : "f"(b), "f"(a));
    return r;
}
// k-word interleave within an 8-word group: [0,4,1,5,2,6,3,7]
__device__ __forceinline__ int perm8(int j) {
    return (j & 4) ? (((j & 3) << 1) | 1) : (j << 1);
}

// ---------------------------------------------------------------------------
// Kernel 0: offsets (1-warp chunked scan) + descending-n block order
// ---------------------------------------------------------------------------
__global__ void scan_kernel(const int* __restrict__ agents, int nB) {
    __shared__ int cnt[65];
    __shared__ int cur[65];
    const int lane = threadIdx.x;
    for (int i = lane; i < 65; i += 32) cnt[i] = 0;
    __syncwarp();

    const int base = lane * 64;
    int s = 0;
    for (int i = 0; i < 64; i++) {
        int idx = base + i;
        if (idx < nB) {
            int a = agents[idx];
            s += a;
            atomicAdd(&cnt[a], 1);
        }
    }
    int inc = s;
#pragma unroll
    for (int d = 1; d < 32; d <<= 1) {
        int v = __shfl_up_sync(0xffffffffu, inc, d);
        if (lane >= d) inc += v;
    }
    int run = inc - s;
    for (int i = 0; i < 64; i++) {
        int idx = base + i;
        if (idx < nB) {
            g_off[idx] = run;
            run += agents[idx];
        }
    }
    __syncwarp();
    if (lane == 0) {
        int acc = 0;
        for (int v = 64; v >= 1; v--) { cur[v] = acc; acc += cnt[v]; }
    }
    __syncwarp();
    for (int i = 0; i < 64; i++) {
        int idx = base + i;
        if (idx < nB) {
            int pos = atomicAdd(&cur[agents[idx]], 1);
            g_order[pos] = idx;
        }
    }
}

// ---------------------------------------------------------------------------
// Kernel 0b: split W1|W2 into packed fp16 hi/lo words
// ---------------------------------------------------------------------------
__global__ void wsplit_kernel(const float* __restrict__ w1,
                              const float* __restrict__ w2) {
    int i = blockIdx.x * 256 + threadIdx.x;
    if (i >= W_WORDS) return;
    int j = 2 * i;
    float x0 = (j < 384 * 128) ? w1[j] : w2[j - 384 * 128];
    float x1 = (j + 1 < 384 * 128) ? w1[j + 1] : w2[j + 1 - 384 * 128];
    __half h0 = __float2half_rn(x0);
    __half h1 = __float2half_rn(x1);
    g_whP[i] = (uint32_t)__half_as_ushort(h0) |
               ((uint32_t)__half_as_ushort(h1) << 16);
    g_wlP[i] = packh(x0 - __half2float(h0), x1 - __half2float(h1));
}

// ---------------------------------------------------------------------------
// MMA wrappers
// ---------------------------------------------------------------------------
__device__ __forceinline__ void mma_f16(
    float* d, const uint32_t* a, uint32_t b0, uint32_t b1)
{
    asm volatile(
        "mma.sync.aligned.m16n8k16.row.col.f32.f16.f16.f32 "
        "{%0,%1,%2,%3}, {%4,%5,%6,%7}, {%8,%9}, {%0,%1,%2,%3};"
        : "+f"(d[0]), "+f"(d[1]), "+f"(d[2]), "+f"(d[3])
        : "r"(a[0]), "r"(a[1]), "r"(a[2]), "r"(a[3]), "r"(b0), "r"(b1));
}
__device__ __forceinline__ void mma_bf16(
    float* d, const uint32_t* a, uint32_t b0, uint32_t b1)
{
    asm volatile(
        "mma.sync.aligned.m16n8k16.row.col.f32.bf16.bf16.f32 "
        "{%0,%1,%2,%3}, {%4,%5,%6,%7}, {%8,%9}, {%0,%1,%2,%3};"
        : "+f"(d[0]), "+f"(d[1]), "+f"(d[2]), "+f"(d[3])
        : "r"(a[0]), "r"(a[1]), "r"(a[2]), "r"(a[3]), "r"(b0), "r"(b1));
}

#define GST 68
#define GEMM_SMEM (3 * 128 * GST * 4)   // 104448 B

// staging helpers: write a packed-word pair (k-words w0=2q, 2q+1) permuted
__device__ __forceinline__ void put_pair(uint32_t* dst, int row, int q,
                                         uint32_t lo, uint32_t hi) {
    int w0 = 2 * q;
    int b2 = row * GST + (w0 & ~7);
    int j0 = w0 & 7;
    dst[b2 + perm8(j0)]     = lo;
    dst[b2 + perm8(j0 + 1)] = hi;
}

// ---------------------------------------------------------------------------
// Fused QKV projection (fp16 2-term, interleaved k layout).
//   Q out: fp16x2 scaled 0.25, permuted head-groups; K out: same; V: fp32.
// ---------------------------------------------------------------------------
__global__ __launch_bounds__(256, 2) void gemm_qkv_kernel(
    const float* __restrict__ X, const uint32_t* __restrict__ Wh,
    const uint32_t* __restrict__ Wl, const float* __restrict__ bias,
    uint32_t* __restrict__ qP, uint32_t* __restrict__ kP,
    float* __restrict__ vF)
{
    extern __shared__ uint32_t sm[];
    uint32_t* Ah = sm;
    uint32_t* Bh = Ah + 128 * GST;
    uint32_t* Bl = Bh + 128 * GST;

    const int tid = threadIdx.x;
    const int m_base = blockIdx.x * 128;
    const int warp = tid >> 5, lane = tid & 31;
    const int wm = warp & 3;
    const int wn = warp >> 2;
    const int g  = lane >> 2;
    const int t  = lane & 3;

    // ---- stage A once ----
#pragma unroll
    for (int i = 0; i < 16; i++) {
        int idx = tid + i * 256;
        int row = idx >> 5;
        int q   = idx & 31;
        float4 x = *(const float4*)(X + (size_t)(m_base + row) * 128 + q * 4);
        put_pair(Ah, row, q, packh(x.x, x.y), packh(x.z, x.w));
    }

    for (int nb = 0; nb < 3; nb++) {
#pragma unroll
        for (int i = 0; i < 16; i++) {
            int idx = tid + i * 256;
            int row = idx >> 5;
            int q   = idx & 31;
            int wr  = nb * 128 + row;
            uint2 wh = *(const uint2*)(Wh + (size_t)wr * 64 + q * 2);
            uint2 wl = *(const uint2*)(Wl + (size_t)wr * 64 + q * 2);
            put_pair(Bh, row, q, wh.x, wh.y);
            put_pair(Bl, row, q, wl.x, wl.y);
        }
        __syncthreads();

        float acc[2][8][4];
#pragma unroll
        for (int i = 0; i < 2; i++)
#pragma unroll
            for (int j = 0; j < 8; j++)
#pragma unroll
                for (int r = 0; r < 4; r++) acc[i][j][r] = 0.f;

#pragma unroll
        for (int ks = 0; ks < 8; ks++) {
            const int kw = ks * 8;
            uint32_t ah[2][4];
#pragma unroll
            for (int mt = 0; mt < 2; mt++) {
                int r0 = (wm * 32 + mt * 16 + g) * GST + kw;
                uint2 a0 = *(const uint2*)(Ah + r0 + 2 * t);
                uint2 a1 = *(const uint2*)(Ah + r0 + 8 * GST + 2 * t);
                ah[mt][0] = a0.x; ah[mt][2] = a0.y;
                ah[mt][1] = a1.x; ah[mt][3] = a1.y;
            }
#pragma unroll
            for (int nt = 0; nt < 8; nt++) {
                int n0 = (wn * 64 + nt * 8 + g) * GST + kw;
                uint2 bh = *(const uint2*)(Bh + n0 + 2 * t);
                uint2 bl = *(const uint2*)(Bl + n0 + 2 * t);
#pragma unroll
                for (int mt = 0; mt < 2; mt++) {
                    mma_f16(acc[mt][nt], ah[mt], bh.x, bh.y);
                    mma_f16(acc[mt][nt], ah[mt], bl.x, bl.y);
                }
            }
        }

        // ---- epilogue ----
        const float scale = (nb == 0) ? 0.25f : 1.f;
#pragma unroll
        for (int nt = 0; nt < 8; nt++) {
            int cn = wn * 64 + nt * 8 + 2 * t;
            float b0 = bias[nb * 128 + cn];
            float b1 = bias[nb * 128 + cn + 1];
#pragma unroll
            for (int mt = 0; mt < 2; mt++) {
                int rm = m_base + wm * 32 + mt * 16 + g;
                float v00 = acc[mt][nt][0] + b0, v01 = acc[mt][nt][1] + b1;
                float v10 = acc[mt][nt][2] + b0, v11 = acc[mt][nt][3] + b1;
                if (nb == 2) {
                    *(float2*)(vF + (size_t)rm * 128 + cn) =
                        make_float2(v00, v01);
                    *(float2*)(vF + (size_t)(rm + 8) * 128 + cn) =
                        make_float2(v10, v11);
                } else {
                    uint32_t* dst = (nb == 0) ? qP : kP;
                    int wcol = cn >> 1;
                    int wdst = (wcol & ~7) + perm8(wcol & 7);
                    dst[(size_t)rm * 64 + wdst] =
                        packh(v00 * scale, v01 * scale);
                    dst[(size_t)(rm + 8) * 64 + wdst] =
                        packh(v10 * scale, v11 * scale);
                }
            }
        }
        if (nb < 2) __syncthreads();
    }
}

// ---------------------------------------------------------------------------
// Out-projection GEMM (fp16 2-term, interleaved k layout)
// ---------------------------------------------------------------------------
__global__ __launch_bounds__(256, 2) void gemm_f16_kernel(
    const float* __restrict__ X, const uint32_t* __restrict__ Wh,
    const uint32_t* __restrict__ Wl, const float* __restrict__ bias,
    float* __restrict__ C, int Ntot)
{
    extern __shared__ uint32_t sm[];
    uint32_t* Ah = sm;
    uint32_t* Bh = Ah + 128 * GST;
    uint32_t* Bl = Bh + 128 * GST;

    const int tid = threadIdx.x;
    const int m_base = blockIdx.x * 128;
    const int n_base = blockIdx.y * 128;
    const int warp = tid >> 5, lane = tid & 31;
    const int wm = warp & 3;
    const int wn = warp >> 2;
    const int g  = lane >> 2;
    const int t  = lane & 3;

#pragma unroll
    for (int i = 0; i < 16; i++) {
        int idx = tid + i * 256;
        int row = idx >> 5;
        int q   = idx & 31;
        float4 x = *(const float4*)(X + (size_t)(m_base + row) * 128 + q * 4);
        put_pair(Ah, row, q, packh(x.x, x.y), packh(x.z, x.w));

        uint2 wh = *(const uint2*)(Wh + (size_t)(n_base + row) * 64 + q * 2);
        uint2 wl = *(const uint2*)(Wl + (size_t)(n_base + row) * 64 + q * 2);
        put_pair(Bh, row, q, wh.x, wh.y);
        put_pair(Bl, row, q, wl.x, wl.y);
    }
    __syncthreads();

    float acc[2][8][4];
#pragma unroll
    for (int i = 0; i < 2; i++)
#pragma unroll
        for (int j = 0; j < 8; j++)
#pragma unroll
            for (int r = 0; r < 4; r++) acc[i][j][r] = 0.f;

#pragma unroll
    for (int ks = 0; ks < 8; ks++) {
        const int kw = ks * 8;
        uint32_t ah[2][4];
#pragma unroll
        for (int mt = 0; mt < 2; mt++) {
            int r0 = (wm * 32 + mt * 16 + g) * GST + kw;
            uint2 a0 = *(const uint2*)(Ah + r0 + 2 * t);
            uint2 a1 = *(const uint2*)(Ah + r0 + 8 * GST + 2 * t);
            ah[mt][0] = a0.x; ah[mt][2] = a0.y;
            ah[mt][1] = a1.x; ah[mt][3] = a1.y;
        }
#pragma unroll
        for (int nt = 0; nt < 8; nt++) {
            int n0 = (wn * 64 + nt * 8 + g) * GST + kw;
            uint2 bh = *(const uint2*)(Bh + n0 + 2 * t);
            uint2 bl = *(const uint2*)(Bl + n0 + 2 * t);
#pragma unroll
            for (int mt = 0; mt < 2; mt++) {
                mma_f16(acc[mt][nt], ah[mt], bh.x, bh.y);
                mma_f16(acc[mt][nt], ah[mt], bl.x, bl.y);
            }
        }
    }

#pragma unroll
    for (int nt = 0; nt < 8; nt++) {
        int cn = n_base + wn * 64 + nt * 8 + 2 * t;
        float b0 = bias[cn], b1 = bias[cn + 1];
#pragma unroll
        for (int mt = 0; mt < 2; mt++) {
            int rm = m_base + wm * 32 + mt * 16 + g;
            float2 v0 = {acc[mt][nt][0] + b0, acc[mt][nt][1] + b1};
            float2 v1 = {acc[mt][nt][2] + b0, acc[mt][nt][3] + b1};
            *(float2*)(C + (size_t)rm * Ntot + cn) = v0;
            *(float2*)(C + (size_t)(rm + 8) * Ntot + cn) = v1;
        }
    }
}

// ---------------------------------------------------------------------------
// Tensor-core ragged attention, mask-free:
//   padded K rows = 0 -> p = exp(0) = 1 exactly; padded V rows = 0 ->
//   d*V contributes 0; fix l by subtracting (npad - n) after reduction.
//   Q/K in permuted fp16 layout (LDG.64 / LDS.64 fragments).
// ---------------------------------------------------------------------------
#define KST 68
#define VAP 132
#define KPK_OFF  0
#define VPK_OFF  (64 * KST)                 // 4352
#define PSUM_OFF (VPK_OFF + 32 * VAP)       // 8576
#define CSUM_OFF (PSUM_OFF + 8 * VAP)       // 9632
#define ATTN_SMEM ((CSUM_OFF + VAP) * 4)    // 39056 B

__global__ __launch_bounds__(256, 4) void attn_mma_kernel(
    const uint32_t* __restrict__ qP, const uint32_t* __restrict__ kP,
    const float* __restrict__ vF, float* __restrict__ ctx,
    const int* __restrict__ agents)
{
    extern __shared__ uint32_t smu[];
    uint32_t* Kpk  = smu + KPK_OFF;
    uint32_t* Vpk  = smu + VPK_OFF;
    float*    psum = (float*)(smu + PSUM_OFF);
    float*    csum = (float*)(smu + CSUM_OFF);

    const int b   = g_order[blockIdx.x];
    const int n   = agents[b];
    const int off = g_off[b];
    const int tid = threadIdx.x;
    const int npad = (n + 15) & ~15;

    // ---- stage K (straight copy; layout already permuted) ----
    for (int idx = tid; idx < npad * 16; idx += 256) {
        int r  = idx >> 4;
        int q4 = (idx & 15) * 4;
        uint4 kw = {0, 0, 0, 0};
        if (r < n)
            kw = *(const uint4*)(kP + (size_t)(off + r) * 64 + q4);
        *(uint4*)(Kpk + r * KST + q4) = kw;
    }

    // ---- stage V (bf16 key-pairs) + fp32 column partial sums ----
    const int c4 = (tid & 31) * 4;
    float vs0 = 0.f, vs1 = 0.f, vs2 = 0.f, vs3 = 0.f;
    for (int idx = tid; idx < npad * 16; idx += 256) {
        int r2 = idx >> 5;
        int r0 = 2 * r2, r1 = r0 + 1;
        float4 va = {0,0,0,0}, vb = {0,0,0,0};
        if (r0 < n)
            va = *(const float4*)(vF + (size_t)(off + r0) * 128 + c4);
        if (r1 < n)
            vb = *(const float4*)(vF + (size_t)(off + r1) * 128 + c4);
        uint4 vp;
        vp.x = packbf(va.x, vb.x);
        vp.y = packbf(va.y, vb.y);
        vp.z = packbf(va.z, vb.z);
        vp.w = packbf(va.w, vb.w);
        *(uint4*)(Vpk + r2 * VAP + c4) = vp;
        vs0 += va.x + vb.x; vs1 += va.y + vb.y;
        vs2 += va.z + vb.z; vs3 += va.w + vb.w;
    }
    *(float4*)(psum + (tid >> 5) * VAP + c4) = make_float4(vs0, vs1, vs2, vs3);
    __syncthreads();
    if (tid < 128) {
        float s = 0.f;
#pragma unroll
        for (int w = 0; w < 8; w++) s += psum[w * VAP + tid];
        csum[tid] = s;
    }
    __syncthreads();

    const int warp = tid >> 5;     // head
    const int lane = tid & 31;
    const int g = lane >> 2;
    const int t = lane & 3;
    const int h16 = warp * 16;
    const int h8  = warp * 8;

    const int nmt = (n + 15) >> 4;
    const float lfix = (float)(npad - n);

    for (int mt = 0; mt < nmt; mt++) {
        // Q fragments: LDG.64 from permuted layout (pre-scaled by 1/4)
        const int qr0 = min(mt * 16 + g, n - 1);
        const int qr1 = min(mt * 16 + 8 + g, n - 1);
        uint2 q0 = *(const uint2*)(qP + (size_t)(off + qr0) * 64 + h8 + 2 * t);
        uint2 q1 = *(const uint2*)(qP + (size_t)(off + qr1) * 64 + h8 + 2 * t);
        uint32_t qa[4];
        qa[0] = q0.x; qa[2] = q0.y;
        qa[1] = q1.x; qa[3] = q1.y;

        float oacc[2][4];
#pragma unroll
        for (int nt = 0; nt < 2; nt++)
#pragma unroll
            for (int r = 0; r < 4; r++) oacc[nt][r] = 0.f;
        float l0 = 0.f, l1 = 0.f;

        for (int kb = 0; kb < npad; kb += 16) {
            // ---- S for two 16q x 8k tiles (LDS.64 fragments) ----
            float sA[4] = {0,0,0,0}, sB[4] = {0,0,0,0};
            const uint32_t* kA = Kpk + (kb + g) * KST + h8;
            uint2 ka2 = *(const uint2*)(kA + 2 * t);
            uint2 kb2 = *(const uint2*)(kA + 8 * KST + 2 * t);
            mma_f16(sA, qa, ka2.x, ka2.y);
            mma_f16(sB, qa, kb2.x, kb2.y);

            // ---- p = exp(s), no masking (padded keys give exactly 1) ----
            float pA0 = __expf(sA[0]);
            float pA1 = __expf(sA[1]);
            float pA2 = __expf(sA[2]);
            float pA3 = __expf(sA[3]);
            float pB0 = __expf(sB[0]);
            float pB1 = __expf(sB[1]);
            float pB2 = __expf(sB[2]);
            float pB3 = __expf(sB[3]);
            l0 += (pA0 + pA1) + (pB0 + pB1);
            l1 += (pA2 + pA3) + (pB2 + pB3);

            // ---- pack D = P-1 into bf16 A-fragment (0 for padded keys) ----
            uint32_t pa[4];
            pa[0] = packbf(pA0 - 1.f, pA1 - 1.f);
            pa[1] = packbf(pA2 - 1.f, pA3 - 1.f);
            pa[2] = packbf(pB0 - 1.f, pB1 - 1.f);
            pa[3] = packbf(pB2 - 1.f, pB3 - 1.f);

            // ---- oacc += D * V (16 keys) ----
#pragma unroll
            for (int nt = 0; nt < 2; nt++) {
                const uint32_t* vp = Vpk + ((kb >> 1) + t) * VAP
                                         + h16 + nt * 8 + g;
                mma_bf16(oacc[nt], pa, vp[0], vp[4 * VAP]);
            }
        }

        // ---- reduce l, remove padded-key contribution, normalize ----
        l0 += __shfl_xor_sync(0xffffffffu, l0, 1);
        l0 += __shfl_xor_sync(0xffffffffu, l0, 2);
        l1 += __shfl_xor_sync(0xffffffffu, l1, 1);
        l1 += __shfl_xor_sync(0xffffffffu, l1, 2);
        const float inv0 = 1.f / (l0 - lfix), inv1 = 1.f / (l1 - lfix);

        const int q0r = mt * 16 + g;
        const int q1r = q0r + 8;
#pragma unroll
        for (int nt = 0; nt < 2; nt++) {
            const int col = h16 + nt * 8 + 2 * t;
            float2 cs = *(float2*)(csum + col);
            if (q0r < n) {
                float2 v = {(cs.x + oacc[nt][0]) * inv0,
                            (cs.y + oacc[nt][1]) * inv0};
                *(float2*)(ctx + (size_t)(off + q0r) * 128 + col) = v;
            }
            if (q1r < n) {
                float2 v = {(cs.x + oacc[nt][2]) * inv1,
                            (cs.y + oacc[nt][3]) * inv1};
                *(float2*)(ctx + (size_t)(off + q1r) * 128 + col) = v;
            }
        }
    }
}

// ---------------------------------------------------------------------------
extern "C" void kernel_launch(void* const* d_in, const int* in_sizes, int n_in,
                              void* d_out, int out_size)
{
    const float* att_in = (const float*)d_in[0];
    const float* w1     = (const float*)d_in[1];
    const float* b1     = (const float*)d_in[2];
    const float* w2     = (const float*)d_in[3];
    const float* b2     = (const float*)d_in[4];
    const int*   agents = (const int*)d_in[5];

    const int M  = in_sizes[0] / 128;   // 66560
    const int nB = in_sizes[5];         // 2048

    float* ctx = nullptr; float* vF = nullptr;
    uint32_t* whp = nullptr; uint32_t* wlp = nullptr;
    uint32_t* qP = nullptr; uint32_t* kP = nullptr;
    cudaGetSymbolAddress((void**)&ctx, g_ctx);
    cudaGetSymbolAddress((void**)&vF,  g_vF);
    cudaGetSymbolAddress((void**)&whp, g_whP);
    cudaGetSymbolAddress((void**)&wlp, g_wlP);
    cudaGetSymbolAddress((void**)&qP,  g_qP);
    cudaGetSymbolAddress((void**)&kP,  g_kP);

    cudaFuncSetAttribute(gemm_qkv_kernel,
                         cudaFuncAttributeMaxDynamicSharedMemorySize, GEMM_SMEM);
    cudaFuncSetAttribute(gemm_f16_kernel,
                         cudaFuncAttributeMaxDynamicSharedMemorySize, GEMM_SMEM);
    cudaFuncSetAttribute(attn_mma_kernel,
                         cudaFuncAttributeMaxDynamicSharedMemorySize, ATTN_SMEM);

    scan_kernel<<<1, 32>>>(agents, nB);
    wsplit_kernel<<<(W_WORDS + 255) / 256, 256>>>(w1, w2);

    gemm_qkv_kernel<<<M / 128, 256, GEMM_SMEM>>>(
        att_in, whp, wlp, b1, qP, kP, vF);

    attn_mma_kernel<<<nB, 256, ATTN_SMEM>>>(qP, kP, vF, ctx, agents);

    gemm_f16_kernel<<<dim3(M / 128, 1), 256, GEMM_SMEM>>>(
        ctx, whp + 384 * 64, wlp + 384 * 64, b2, (float*)d_out, 128);
}

// round 13
// speedup vs baseline: 1.3883x; 1.3883x over previous
#include <cuda_runtime.h>
#include <cuda_fp16.h>
#include <cuda_bf16.h>
#include <cstdint>

#define MAX_TOTAL 66560
#define MAX_B     2048
#define W_TOTAL   ((384 + 128) * 128)
#define W_WORDS   (W_TOTAL / 2)

__device__ float    g_ctx[(size_t)MAX_TOTAL * 128];
__device__ int      g_off[MAX_B];
__device__ int      g_order[MAX_B];
__device__ uint32_t g_whP[W_WORDS];                    // packed fp16x2 W
__device__ uint32_t g_qP[(size_t)MAX_TOTAL * 64];      // Q/4 fp16x2, perm k
__device__ uint32_t g_kP[(size_t)MAX_TOTAL * 64];      // K fp16x2, perm k
__device__ float    g_vF[(size_t)MAX_TOTAL * 128];     // V fp32

__device__ __forceinline__ uint32_t packh(float a, float b) {
    uint32_t r;
    asm("cvt.rn.f16x2.f32 %0, %1, %2;" : "=r"(r) : "f"(b), "f"(a));
    return r;   // lo = a, hi = b
}
__device__ __forceinline__ uint32_t packbf(float a, float b) {
    uint32_t r;
    asm("cvt.rn.bf16x2.f32 %0, %1, %2;" : "=r"(r) : "f"(b), "f"(a));
    return r;
}
// k-word interleave within an 8-word group: [0,4,1,5,2,6,3,7]
__device__ __forceinline__ int perm8(int j) {
    return (j & 4) ? (((j & 3) << 1) | 1) : (j << 1);
}

// ---------------------------------------------------------------------------
// Kernel 0: offsets (1-warp chunked scan) + descending-n block order
// ---------------------------------------------------------------------------
__global__ void scan_kernel(const int* __restrict__ agents, int nB) {
    __shared__ int cnt[65];
    __shared__ int cur[65];
    const int lane = threadIdx.x;
    for (int i = lane; i < 65; i += 32) cnt[i] = 0;
    __syncwarp();

    const int base = lane * 64;
    int s = 0;
    for (int i = 0; i < 64; i++) {
        int idx = base + i;
        if (idx < nB) {
            int a = agents[idx];
            s += a;
            atomicAdd(&cnt[a], 1);
        }
    }
    int inc = s;
#pragma unroll
    for (int d = 1; d < 32; d <<= 1) {
        int v = __shfl_up_sync(0xffffffffu, inc, d);
        if (lane >= d) inc += v;
    }
    int run = inc - s;
    for (int i = 0; i < 64; i++) {
        int idx = base + i;
        if (idx < nB) {
            g_off[idx] = run;
            run += agents[idx];
        }
    }
    __syncwarp();
    if (lane == 0) {
        int acc = 0;
        for (int v = 64; v >= 1; v--) { cur[v] = acc; acc += cnt[v]; }
    }
    __syncwarp();
    for (int i = 0; i < 64; i++) {
        int idx = base + i;
        if (idx < nB) {
            int pos = atomicAdd(&cur[agents[idx]], 1);
            g_order[pos] = idx;
        }
    }
}

// ---------------------------------------------------------------------------
// Kernel 0b: W1|W2 -> packed fp16 words (single term)
// ---------------------------------------------------------------------------
__global__ void wsplit_kernel(const float* __restrict__ w1,
                              const float* __restrict__ w2) {
    int i = blockIdx.x * 256 + threadIdx.x;
    if (i >= W_WORDS) return;
    int j = 2 * i;
    float x0 = (j < 384 * 128) ? w1[j] : w2[j - 384 * 128];
    float x1 = (j + 1 < 384 * 128) ? w1[j + 1] : w2[j + 1 - 384 * 128];
    g_whP[i] = packh(x0, x1);
}

// ---------------------------------------------------------------------------
// MMA wrappers
// ---------------------------------------------------------------------------
__device__ __forceinline__ void mma_f16(
    float* d, const uint32_t* a, uint32_t b0, uint32_t b1)
{
    asm volatile(
        "mma.sync.aligned.m16n8k16.row.col.f32.f16.f16.f32 "
        "{%0,%1,%2,%3}, {%4,%5,%6,%7}, {%8,%9}, {%0,%1,%2,%3};"
        : "+f"(d[0]), "+f"(d[1]), "+f"(d[2]), "+f"(d[3])
        : "r"(a[0]), "r"(a[1]), "r"(a[2]), "r"(a[3]), "r"(b0), "r"(b1));
}
__device__ __forceinline__ void mma_bf16(
    float* d, const uint32_t* a, uint32_t b0, uint32_t b1)
{
    asm volatile(
        "mma.sync.aligned.m16n8k16.row.col.f32.bf16.bf16.f32 "
        "{%0,%1,%2,%3}, {%4,%5,%6,%7}, {%8,%9}, {%0,%1,%2,%3};"
        : "+f"(d[0]), "+f"(d[1]), "+f"(d[2]), "+f"(d[3])
        : "r"(a[0]), "r"(a[1]), "r"(a[2]), "r"(a[3]), "r"(b0), "r"(b1));
}

#define GST 68
#define GEMM_SMEM (2 * 128 * GST * 4)   // 69632 B (A + B, single term)

// ---------------------------------------------------------------------------
// Fused QKV projection, 1-term fp16: C ~= Xh @ Wh^T + bias.
//   Non-interleaved smem (scalar fragment LDS, banks 4g+t: conflict-free).
//   Q out: fp16x2 scaled 0.25, PERMUTED word layout; K out: same; V: fp32.
// ---------------------------------------------------------------------------
__global__ __launch_bounds__(256, 2) void gemm_qkv_kernel(
    const float* __restrict__ X, const uint32_t* __restrict__ Wh,
    const float* __restrict__ bias,
    uint32_t* __restrict__ qP, uint32_t* __restrict__ kP,
    float* __restrict__ vF)
{
    extern __shared__ uint32_t sm[];
    uint32_t* Ah = sm;
    uint32_t* Bh = Ah + 128 * GST;

    const int tid = threadIdx.x;
    const int m_base = blockIdx.x * 128;
    const int warp = tid >> 5, lane = tid & 31;
    const int wm = warp & 3;
    const int wn = warp >> 2;
    const int g  = lane >> 2;
    const int t  = lane & 3;

    // ---- stage A once ----
#pragma unroll
    for (int i = 0; i < 16; i++) {
        int idx = tid + i * 256;
        int row = idx >> 5;
        int q   = idx & 31;
        float4 x = *(const float4*)(X + (size_t)(m_base + row) * 128 + q * 4);
        uint2 hv;
        hv.x = packh(x.x, x.y);
        hv.y = packh(x.z, x.w);
        *(uint2*)(Ah + row * GST + q * 2) = hv;
    }

    for (int nb = 0; nb < 3; nb++) {
#pragma unroll
        for (int i = 0; i < 16; i++) {
            int idx = tid + i * 256;
            int row = idx >> 5;
            int q   = idx & 31;
            uint2 wh = *(const uint2*)(Wh + (size_t)(nb * 128 + row) * 64
                                          + q * 2);
            *(uint2*)(Bh + row * GST + q * 2) = wh;
        }
        __syncthreads();

        float acc[2][8][4];
#pragma unroll
        for (int i = 0; i < 2; i++)
#pragma unroll
            for (int j = 0; j < 8; j++)
#pragma unroll
                for (int r = 0; r < 4; r++) acc[i][j][r] = 0.f;

#pragma unroll
        for (int ks = 0; ks < 8; ks++) {
            const int kw = ks * 8;
            uint32_t ah[2][4];
#pragma unroll
            for (int mt = 0; mt < 2; mt++) {
                int r0 = (wm * 32 + mt * 16 + g) * GST + kw;
                int r1 = r0 + 8 * GST;
                ah[mt][0] = Ah[r0 + t];     ah[mt][1] = Ah[r1 + t];
                ah[mt][2] = Ah[r0 + t + 4]; ah[mt][3] = Ah[r1 + t + 4];
            }
#pragma unroll
            for (int nt = 0; nt < 8; nt++) {
                int n0 = (wn * 64 + nt * 8 + g) * GST + kw;
                uint32_t bh0 = Bh[n0 + t], bh1 = Bh[n0 + t + 4];
#pragma unroll
                for (int mt = 0; mt < 2; mt++)
                    mma_f16(acc[mt][nt], ah[mt], bh0, bh1);
            }
        }

        // ---- epilogue ----
        const float scale = (nb == 0) ? 0.25f : 1.f;
#pragma unroll
        for (int nt = 0; nt < 8; nt++) {
            int cn = wn * 64 + nt * 8 + 2 * t;
            float b0 = bias[nb * 128 + cn];
            float b1 = bias[nb * 128 + cn + 1];
#pragma unroll
            for (int mt = 0; mt < 2; mt++) {
                int rm = m_base + wm * 32 + mt * 16 + g;
                float v00 = acc[mt][nt][0] + b0, v01 = acc[mt][nt][1] + b1;
                float v10 = acc[mt][nt][2] + b0, v11 = acc[mt][nt][3] + b1;
                if (nb == 2) {
                    *(float2*)(vF + (size_t)rm * 128 + cn) =
                        make_float2(v00, v01);
                    *(float2*)(vF + (size_t)(rm + 8) * 128 + cn) =
                        make_float2(v10, v11);
                } else {
                    uint32_t* dst = (nb == 0) ? qP : kP;
                    int wcol = cn >> 1;
                    int wdst = (wcol & ~7) + perm8(wcol & 7);
                    dst[(size_t)rm * 64 + wdst] =
                        packh(v00 * scale, v01 * scale);
                    dst[(size_t)(rm + 8) * 64 + wdst] =
                        packh(v10 * scale, v11 * scale);
                }
            }
        }
        if (nb < 2) __syncthreads();
    }
}

// ---------------------------------------------------------------------------
// Out-projection GEMM, 1-term fp16 (non-interleaved smem)
// ---------------------------------------------------------------------------
__global__ __launch_bounds__(256, 2) void gemm_f16_kernel(
    const float* __restrict__ X, const uint32_t* __restrict__ Wh,
    const float* __restrict__ bias, float* __restrict__ C, int Ntot)
{
    extern __shared__ uint32_t sm[];
    uint32_t* Ah = sm;
    uint32_t* Bh = Ah + 128 * GST;

    const int tid = threadIdx.x;
    const int m_base = blockIdx.x * 128;
    const int warp = tid >> 5, lane = tid & 31;
    const int wm = warp & 3;
    const int wn = warp >> 2;
    const int g  = lane >> 2;
    const int t  = lane & 3;

#pragma unroll
    for (int i = 0; i < 16; i++) {
        int idx = tid + i * 256;
        int row = idx >> 5;
        int q   = idx & 31;
        float4 x = *(const float4*)(X + (size_t)(m_base + row) * 128 + q * 4);
        uint2 hv;
        hv.x = packh(x.x, x.y);
        hv.y = packh(x.z, x.w);
        *(uint2*)(Ah + row * GST + q * 2) = hv;

        uint2 wh = *(const uint2*)(Wh + (size_t)row * 64 + q * 2);
        *(uint2*)(Bh + row * GST + q * 2) = wh;
    }
    __syncthreads();

    float acc[2][8][4];
#pragma unroll
    for (int i = 0; i < 2; i++)
#pragma unroll
        for (int j = 0; j < 8; j++)
#pragma unroll
            for (int r = 0; r < 4; r++) acc[i][j][r] = 0.f;

#pragma unroll
    for (int ks = 0; ks < 8; ks++) {
        const int kw = ks * 8;
        uint32_t ah[2][4];
#pragma unroll
        for (int mt = 0; mt < 2; mt++) {
            int r0 = (wm * 32 + mt * 16 + g) * GST + kw;
            int r1 = r0 + 8 * GST;
            ah[mt][0] = Ah[r0 + t];     ah[mt][1] = Ah[r1 + t];
            ah[mt][2] = Ah[r0 + t + 4]; ah[mt][3] = Ah[r1 + t + 4];
        }
#pragma unroll
        for (int nt = 0; nt < 8; nt++) {
            int n0 = (wn * 64 + nt * 8 + g) * GST + kw;
            uint32_t bh0 = Bh[n0 + t], bh1 = Bh[n0 + t + 4];
#pragma unroll
            for (int mt = 0; mt < 2; mt++)
                mma_f16(acc[mt][nt], ah[mt], bh0, bh1);
        }
    }

#pragma unroll
    for (int nt = 0; nt < 8; nt++) {
        int cn = wn * 64 + nt * 8 + 2 * t;
        float b0 = bias[cn], b1 = bias[cn + 1];
#pragma unroll
        for (int mt = 0; mt < 2; mt++) {
            int rm = m_base + wm * 32 + mt * 16 + g;
            float2 v0 = {acc[mt][nt][0] + b0, acc[mt][nt][1] + b1};
            float2 v1 = {acc[mt][nt][2] + b0, acc[mt][nt][3] + b1};
            *(float2*)(C + (size_t)rm * Ntot + cn) = v0;
            *(float2*)(C + (size_t)(rm + 8) * Ntot + cn) = v1;
        }
    }
}

// ---------------------------------------------------------------------------
// Tensor-core ragged attention (unchanged from R12: 34.6us measured).
//   Mask-free (padded K rows = 0 -> p = 1; l fixed by -(npad-n));
//   Q/K permuted fp16 layout (LDG.64 / LDS.64 fragments);
//   O = (colsum(V) + (P-1)*V)/l, (P-1) in bf16; sorted block order.
// ---------------------------------------------------------------------------
#define KST 68
#define VAP 132
#define KPK_OFF  0
#define VPK_OFF  (64 * KST)                 // 4352
#define PSUM_OFF (VPK_OFF + 32 * VAP)       // 8576
#define CSUM_OFF (PSUM_OFF + 8 * VAP)       // 9632
#define ATTN_SMEM ((CSUM_OFF + VAP) * 4)    // 39056 B

__global__ __launch_bounds__(256, 4) void attn_mma_kernel(
    const uint32_t* __restrict__ qP, const uint32_t* __restrict__ kP,
    const float* __restrict__ vF, float* __restrict__ ctx,
    const int* __restrict__ agents)
{
    extern __shared__ uint32_t smu[];
    uint32_t* Kpk  = smu + KPK_OFF;
    uint32_t* Vpk  = smu + VPK_OFF;
    float*    psum = (float*)(smu + PSUM_OFF);
    float*    csum = (float*)(smu + CSUM_OFF);

    const int b   = g_order[blockIdx.x];
    const int n   = agents[b];
    const int off = g_off[b];
    const int tid = threadIdx.x;
    const int npad = (n + 15) & ~15;

    for (int idx = tid; idx < npad * 16; idx += 256) {
        int r  = idx >> 4;
        int q4 = (idx & 15) * 4;
        uint4 kw = {0, 0, 0, 0};
        if (r < n)
            kw = *(const uint4*)(kP + (size_t)(off + r) * 64 + q4);
        *(uint4*)(Kpk + r * KST + q4) = kw;
    }

    const int c4 = (tid & 31) * 4;
    float vs0 = 0.f, vs1 = 0.f, vs2 = 0.f, vs3 = 0.f;
    for (int idx = tid; idx < npad * 16; idx += 256) {
        int r2 = idx >> 5;
        int r0 = 2 * r2, r1 = r0 + 1;
        float4 va = {0,0,0,0}, vb = {0,0,0,0};
        if (r0 < n)
            va = *(const float4*)(vF + (size_t)(off + r0) * 128 + c4);
        if (r1 < n)
            vb = *(const float4*)(vF + (size_t)(off + r1) * 128 + c4);
        uint4 vp;
        vp.x = packbf(va.x, vb.x);
        vp.y = packbf(va.y, vb.y);
        vp.z = packbf(va.z, vb.z);
        vp.w = packbf(va.w, vb.w);
        *(uint4*)(Vpk + r2 * VAP + c4) = vp;
        vs0 += va.x + vb.x; vs1 += va.y + vb.y;
        vs2 += va.z + vb.z; vs3 += va.w + vb.w;
    }
    *(float4*)(psum + (tid >> 5) * VAP + c4) = make_float4(vs0, vs1, vs2, vs3);
    __syncthreads();
    if (tid < 128) {
        float s = 0.f;
#pragma unroll
        for (int w = 0; w < 8; w++) s += psum[w * VAP + tid];
        csum[tid] = s;
    }
    __syncthreads();

    const int warp = tid >> 5;
    const int lane = tid & 31;
    const int g = lane >> 2;
    const int t = lane & 3;
    const int h16 = warp * 16;
    const int h8  = warp * 8;

    const int nmt = (n + 15) >> 4;
    const float lfix = (float)(npad - n);

    for (int mt = 0; mt < nmt; mt++) {
        const int qr0 = min(mt * 16 + g, n - 1);
        const int qr1 = min(mt * 16 + 8 + g, n - 1);
        uint2 q0 = *(const uint2*)(qP + (size_t)(off + qr0) * 64 + h8 + 2 * t);
        uint2 q1 = *(const uint2*)(qP + (size_t)(off + qr1) * 64 + h8 + 2 * t);
        uint32_t qa[4];
        qa[0] = q0.x; qa[2] = q0.y;
        qa[1] = q1.x; qa[3] = q1.y;

        float oacc[2][4];
#pragma unroll
        for (int nt = 0; nt < 2; nt++)
#pragma unroll
            for (int r = 0; r < 4; r++) oacc[nt][r] = 0.f;
        float l0 = 0.f, l1 = 0.f;

        for (int kb = 0; kb < npad; kb += 16) {
            float sA[4] = {0,0,0,0}, sB[4] = {0,0,0,0};
            const uint32_t* kA = Kpk + (kb + g) * KST + h8;
            uint2 ka2 = *(const uint2*)(kA + 2 * t);
            uint2 kb2 = *(const uint2*)(kA + 8 * KST + 2 * t);
            mma_f16(sA, qa, ka2.x, ka2.y);
            mma_f16(sB, qa, kb2.x, kb2.y);

            float pA0 = __expf(sA[0]);
            float pA1 = __expf(sA[1]);
            float pA2 = __expf(sA[2]);
            float pA3 = __expf(sA[3]);
            float pB0 = __expf(sB[0]);
            float pB1 = __expf(sB[1]);
            float pB2 = __expf(sB[2]);
            float pB3 = __expf(sB[3]);
            l0 += (pA0 + pA1) + (pB0 + pB1);
            l1 += (pA2 + pA3) + (pB2 + pB3);

            uint32_t pa[4];
            pa[0] = packbf(pA0 - 1.f, pA1 - 1.f);
            pa[1] = packbf(pA2 - 1.f, pA3 - 1.f);
            pa[2] = packbf(pB0 - 1.f, pB1 - 1.f);
            pa[3] = packbf(pB2 - 1.f, pB3 - 1.f);

#pragma unroll
            for (int nt = 0; nt < 2; nt++) {
                const uint32_t* vp = Vpk + ((kb >> 1) + t) * VAP
                                         + h16 + nt * 8 + g;
                mma_bf16(oacc[nt], pa, vp[0], vp[4 * VAP]);
            }
        }

        l0 += __shfl_xor_sync(0xffffffffu, l0, 1);
        l0 += __shfl_xor_sync(0xffffffffu, l0, 2);
        l1 += __shfl_xor_sync(0xffffffffu, l1, 1);
        l1 += __shfl_xor_sync(0xffffffffu, l1, 2);
        const float inv0 = 1.f / (l0 - lfix), inv1 = 1.f / (l1 - lfix);

        const int q0r = mt * 16 + g;
        const int q1r = q0r + 8;
#pragma unroll
        for (int nt = 0; nt < 2; nt++) {
            const int col = h16 + nt * 8 + 2 * t;
            float2 cs = *(float2*)(csum + col);
            if (q0r < n) {
                float2 v = {(cs.x + oacc[nt][0]) * inv0,
                            (cs.y + oacc[nt][1]) * inv0};
                *(float2*)(ctx + (size_t)(off + q0r) * 128 + col) = v;
            }
            if (q1r < n) {
                float2 v = {(cs.x + oacc[nt][2]) * inv1,
                            (cs.y + oacc[nt][3]) * inv1};
                *(float2*)(ctx + (size_t)(off + q1r) * 128 + col) = v;
            }
        }
    }
}

// ---------------------------------------------------------------------------
extern "C" void kernel_launch(void* const* d_in, const int* in_sizes, int n_in,
                              void* d_out, int out_size)
{
    const float* att_in = (const float*)d_in[0];
    const float* w1     = (const float*)d_in[1];
    const float* b1     = (const float*)d_in[2];
    const float* w2     = (const float*)d_in[3];
    const float* b2     = (const float*)d_in[4];
    const int*   agents = (const int*)d_in[5];

    const int M  = in_sizes[0] / 128;   // 66560
    const int nB = in_sizes[5];         // 2048

    float* ctx = nullptr; float* vF = nullptr;
    uint32_t* whp = nullptr;
    uint32_t* qP = nullptr; uint32_t* kP = nullptr;
    cudaGetSymbolAddress((void**)&ctx, g_ctx);
    cudaGetSymbolAddress((void**)&vF,  g_vF);
    cudaGetSymbolAddress((void**)&whp, g_whP);
    cudaGetSymbolAddress((void**)&qP,  g_qP);
    cudaGetSymbolAddress((void**)&kP,  g_kP);

    cudaFuncSetAttribute(gemm_qkv_kernel,
                         cudaFuncAttributeMaxDynamicSharedMemorySize, GEMM_SMEM);
    cudaFuncSetAttribute(gemm_f16_kernel,
                         cudaFuncAttributeMaxDynamicSharedMemorySize, GEMM_SMEM);
    cudaFuncSetAttribute(attn_mma_kernel,
                         cudaFuncAttributeMaxDynamicSharedMemorySize, ATTN_SMEM);

    scan_kernel<<<1, 32>>>(agents, nB);
    wsplit_kernel<<<(W_WORDS + 255) / 256, 256>>>(w1, w2);

    gemm_qkv_kernel<<<M / 128, 256, GEMM_SMEM>>>(
        att_in, whp, b1, qP, kP, vF);

    attn_mma_kernel<<<nB, 256, ATTN_SMEM>>>(qP, kP, vF, ctx, agents);

    gemm_f16_kernel<<<M / 128, 256, GEMM_SMEM>>>(
        ctx, whp + 384 * 64, b2, (float*)d_out, 128);
}

// round 14
// speedup vs baseline: 1.4568x; 1.0494x over previous
#include <cuda_runtime.h>
#include <cuda_fp16.h>
#include <cstdint>

#define MAX_TOTAL 66560
#define MAX_B     2048
#define W_TOTAL   ((384 + 128) * 128)
#define W_WORDS   (W_TOTAL / 2)

__device__ uint32_t g_ctxP[(size_t)MAX_TOTAL * 64];    // attn out, fp16x2
__device__ int      g_off[MAX_B];
__device__ int      g_order[MAX_B];
__device__ uint32_t g_whP[W_WORDS];                    // packed fp16x2 W
__device__ uint32_t g_qP[(size_t)MAX_TOTAL * 64];      // Q/4 fp16x2, perm k
__device__ uint32_t g_kP[(size_t)MAX_TOTAL * 64];      // K fp16x2, perm k
__device__ float    g_vF[(size_t)MAX_TOTAL * 128];     // V fp32

__device__ __forceinline__ uint32_t packh(float a, float b) {
    uint32_t r;
    asm("cvt.rn.f16x2.f32 %0, %1, %2;" : "=r"(r) : "f"(b), "f"(a));
    return r;   // lo = a, hi = b
}
// k-word interleave within an 8-word group: [0,4,1,5,2,6,3,7]
__device__ __forceinline__ int perm8(int j) {
    return (j & 4) ? (((j & 3) << 1) | 1) : (j << 1);
}

// ---------------------------------------------------------------------------
// Kernel 0: offsets (1-warp chunked scan) + descending-n block order
// ---------------------------------------------------------------------------
__global__ void scan_kernel(const int* __restrict__ agents, int nB) {
    __shared__ int cnt[65];
    __shared__ int cur[65];
    const int lane = threadIdx.x;
    for (int i = lane; i < 65; i += 32) cnt[i] = 0;
    __syncwarp();

    const int base = lane * 64;
    int s = 0;
    for (int i = 0; i < 64; i++) {
        int idx = base + i;
        if (idx < nB) {
            int a = agents[idx];
            s += a;
            atomicAdd(&cnt[a], 1);
        }
    }
    int inc = s;
#pragma unroll
    for (int d = 1; d < 32; d <<= 1) {
        int v = __shfl_up_sync(0xffffffffu, inc, d);
        if (lane >= d) inc += v;
    }
    int run = inc - s;
    for (int i = 0; i < 64; i++) {
        int idx = base + i;
        if (idx < nB) {
            g_off[idx] = run;
            run += agents[idx];
        }
    }
    __syncwarp();
    if (lane == 0) {
        int acc = 0;
        for (int v = 64; v >= 1; v--) { cur[v] = acc; acc += cnt[v]; }
    }
    __syncwarp();
    for (int i = 0; i < 64; i++) {
        int idx = base + i;
        if (idx < nB) {
            int pos = atomicAdd(&cur[agents[idx]], 1);
            g_order[pos] = idx;
        }
    }
}

// ---------------------------------------------------------------------------
// Kernel 0b: W1|W2 -> packed fp16 words
// ---------------------------------------------------------------------------
__global__ void wsplit_kernel(const float* __restrict__ w1,
                              const float* __restrict__ w2) {
    int i = blockIdx.x * 256 + threadIdx.x;
    if (i >= W_WORDS) return;
    int j = 2 * i;
    float x0 = (j < 384 * 128) ? w1[j] : w2[j - 384 * 128];
    float x1 = (j + 1 < 384 * 128) ? w1[j + 1] : w2[j + 1 - 384 * 128];
    g_whP[i] = packh(x0, x1);
}

// ---------------------------------------------------------------------------
// MMA wrapper
// ---------------------------------------------------------------------------
__device__ __forceinline__ void mma_f16(
    float* d, const uint32_t* a, uint32_t b0, uint32_t b1)
{
    asm volatile(
        "mma.sync.aligned.m16n8k16.row.col.f32.f16.f16.f32 "
        "{%0,%1,%2,%3}, {%4,%5,%6,%7}, {%8,%9}, {%0,%1,%2,%3};"
        : "+f"(d[0]), "+f"(d[1]), "+f"(d[2]), "+f"(d[3])
        : "r"(a[0]), "r"(a[1]), "r"(a[2]), "r"(a[3]), "r"(b0), "r"(b1));
}

#define GST 68
#define GEMM_SMEM (2 * 128 * GST * 4)   // 69632 B

// ---------------------------------------------------------------------------
// Fused QKV projection, 1-term fp16 (unchanged from R13)
// ---------------------------------------------------------------------------
__global__ __launch_bounds__(256, 2) void gemm_qkv_kernel(
    const float* __restrict__ X, const uint32_t* __restrict__ Wh,
    const float* __restrict__ bias,
    uint32_t* __restrict__ qP, uint32_t* __restrict__ kP,
    float* __restrict__ vF)
{
    extern __shared__ uint32_t sm[];
    uint32_t* Ah = sm;
    uint32_t* Bh = Ah + 128 * GST;

    const int tid = threadIdx.x;
    const int m_base = blockIdx.x * 128;
    const int warp = tid >> 5, lane = tid & 31;
    const int wm = warp & 3;
    const int wn = warp >> 2;
    const int g  = lane >> 2;
    const int t  = lane & 3;

#pragma unroll
    for (int i = 0; i < 16; i++) {
        int idx = tid + i * 256;
        int row = idx >> 5;
        int q   = idx & 31;
        float4 x = *(const float4*)(X + (size_t)(m_base + row) * 128 + q * 4);
        uint2 hv;
        hv.x = packh(x.x, x.y);
        hv.y = packh(x.z, x.w);
        *(uint2*)(Ah + row * GST + q * 2) = hv;
    }

    for (int nb = 0; nb < 3; nb++) {
#pragma unroll
        for (int i = 0; i < 16; i++) {
            int idx = tid + i * 256;
            int row = idx >> 5;
            int q   = idx & 31;
            uint2 wh = *(const uint2*)(Wh + (size_t)(nb * 128 + row) * 64
                                          + q * 2);
            *(uint2*)(Bh + row * GST + q * 2) = wh;
        }
        __syncthreads();

        float acc[2][8][4];
#pragma unroll
        for (int i = 0; i < 2; i++)
#pragma unroll
            for (int j = 0; j < 8; j++)
#pragma unroll
                for (int r = 0; r < 4; r++) acc[i][j][r] = 0.f;

#pragma unroll
        for (int ks = 0; ks < 8; ks++) {
            const int kw = ks * 8;
            uint32_t ah[2][4];
#pragma unroll
            for (int mt = 0; mt < 2; mt++) {
                int r0 = (wm * 32 + mt * 16 + g) * GST + kw;
                int r1 = r0 + 8 * GST;
                ah[mt][0] = Ah[r0 + t];     ah[mt][1] = Ah[r1 + t];
                ah[mt][2] = Ah[r0 + t + 4]; ah[mt][3] = Ah[r1 + t + 4];
            }
#pragma unroll
            for (int nt = 0; nt < 8; nt++) {
                int n0 = (wn * 64 + nt * 8 + g) * GST + kw;
                uint32_t bh0 = Bh[n0 + t], bh1 = Bh[n0 + t + 4];
#pragma unroll
                for (int mt = 0; mt < 2; mt++)
                    mma_f16(acc[mt][nt], ah[mt], bh0, bh1);
            }
        }

        const float scale = (nb == 0) ? 0.25f : 1.f;
#pragma unroll
        for (int nt = 0; nt < 8; nt++) {
            int cn = wn * 64 + nt * 8 + 2 * t;
            float b0 = bias[nb * 128 + cn];
            float b1 = bias[nb * 128 + cn + 1];
#pragma unroll
            for (int mt = 0; mt < 2; mt++) {
                int rm = m_base + wm * 32 + mt * 16 + g;
                float v00 = acc[mt][nt][0] + b0, v01 = acc[mt][nt][1] + b1;
                float v10 = acc[mt][nt][2] + b0, v11 = acc[mt][nt][3] + b1;
                if (nb == 2) {
                    *(float2*)(vF + (size_t)rm * 128 + cn) =
                        make_float2(v00, v01);
                    *(float2*)(vF + (size_t)(rm + 8) * 128 + cn) =
                        make_float2(v10, v11);
                } else {
                    uint32_t* dst = (nb == 0) ? qP : kP;
                    int wcol = cn >> 1;
                    int wdst = (wcol & ~7) + perm8(wcol & 7);
                    dst[(size_t)rm * 64 + wdst] =
                        packh(v00 * scale, v01 * scale);
                    dst[(size_t)(rm + 8) * 64 + wdst] =
                        packh(v10 * scale, v11 * scale);
                }
            }
        }
        if (nb < 2) __syncthreads();
    }
}

// ---------------------------------------------------------------------------
// Out-projection GEMM: A comes PRE-PACKED fp16 (ctxP) -> staging is a copy.
// ---------------------------------------------------------------------------
__global__ __launch_bounds__(256, 2) void gemm_out_kernel(
    const uint32_t* __restrict__ Xp, const uint32_t* __restrict__ Wh,
    const float* __restrict__ bias, float* __restrict__ C)
{
    extern __shared__ uint32_t sm[];
    uint32_t* Ah = sm;
    uint32_t* Bh = Ah + 128 * GST;

    const int tid = threadIdx.x;
    const int m_base = blockIdx.x * 128;
    const int warp = tid >> 5, lane = tid & 31;
    const int wm = warp & 3;
    const int wn = warp >> 2;
    const int g  = lane >> 2;
    const int t  = lane & 3;

#pragma unroll
    for (int i = 0; i < 16; i++) {
        int idx = tid + i * 256;
        int row = idx >> 5;
        int q   = idx & 31;
        uint2 hv = *(const uint2*)(Xp + (size_t)(m_base + row) * 64 + q * 2);
        *(uint2*)(Ah + row * GST + q * 2) = hv;
        uint2 wh = *(const uint2*)(Wh + (size_t)row * 64 + q * 2);
        *(uint2*)(Bh + row * GST + q * 2) = wh;
    }
    __syncthreads();

    float acc[2][8][4];
#pragma unroll
    for (int i = 0; i < 2; i++)
#pragma unroll
        for (int j = 0; j < 8; j++)
#pragma unroll
            for (int r = 0; r < 4; r++) acc[i][j][r] = 0.f;

#pragma unroll
    for (int ks = 0; ks < 8; ks++) {
        const int kw = ks * 8;
        uint32_t ah[2][4];
#pragma unroll
        for (int mt = 0; mt < 2; mt++) {
            int r0 = (wm * 32 + mt * 16 + g) * GST + kw;
            int r1 = r0 + 8 * GST;
            ah[mt][0] = Ah[r0 + t];     ah[mt][1] = Ah[r1 + t];
            ah[mt][2] = Ah[r0 + t + 4]; ah[mt][3] = Ah[r1 + t + 4];
        }
#pragma unroll
        for (int nt = 0; nt < 8; nt++) {
            int n0 = (wn * 64 + nt * 8 + g) * GST + kw;
            uint32_t bh0 = Bh[n0 + t], bh1 = Bh[n0 + t + 4];
#pragma unroll
            for (int mt = 0; mt < 2; mt++)
                mma_f16(acc[mt][nt], ah[mt], bh0, bh1);
        }
    }

#pragma unroll
    for (int nt = 0; nt < 8; nt++) {
        int cn = wn * 64 + nt * 8 + 2 * t;
        float b0 = bias[cn], b1 = bias[cn + 1];
#pragma unroll
        for (int mt = 0; mt < 2; mt++) {
            int rm = m_base + wm * 32 + mt * 16 + g;
            float2 v0 = {acc[mt][nt][0] + b0, acc[mt][nt][1] + b1};
            float2 v1 = {acc[mt][nt][2] + b0, acc[mt][nt][3] + b1};
            *(float2*)(C + (size_t)rm * 128 + cn) = v0;
            *(float2*)(C + (size_t)(rm + 8) * 128 + cn) = v1;
        }
    }
}

// ---------------------------------------------------------------------------
// Tensor-core ragged attention, direct-P version:
//   S via fp16 mma (permuted layouts, LDG.64/LDS.64 fragments, mask-free);
//   P in fp16 straight into the A-fragment; O = P*V via fp16 mma
//   (padded keys: p = 1, V = 0 -> zero contribution; l -= (npad - n)).
//   No column sums, no psum/csum. Output written as packed fp16 (= exactly
//   what the out-GEMM would round to anyway).
// ---------------------------------------------------------------------------
#define KST 68
#define VAP 132
#define KPK_OFF  0
#define VPK_OFF  (64 * KST)                 // 4352
#define ATTN_SMEM ((VPK_OFF + 32 * VAP) * 4)   // 34304 B

__global__ __launch_bounds__(256, 4) void attn_mma_kernel(
    const uint32_t* __restrict__ qP, const uint32_t* __restrict__ kP,
    const float* __restrict__ vF, uint32_t* __restrict__ ctxP,
    const int* __restrict__ agents)
{
    extern __shared__ uint32_t smu[];
    uint32_t* Kpk = smu + KPK_OFF;
    uint32_t* Vpk = smu + VPK_OFF;

    const int b   = g_order[blockIdx.x];
    const int n   = agents[b];
    const int off = g_off[b];
    const int tid = threadIdx.x;
    const int npad = (n + 15) & ~15;

    // ---- stage K (straight permuted copy) ----
    for (int idx = tid; idx < npad * 16; idx += 256) {
        int r  = idx >> 4;
        int q4 = (idx & 15) * 4;
        uint4 kw = {0, 0, 0, 0};
        if (r < n)
            kw = *(const uint4*)(kP + (size_t)(off + r) * 64 + q4);
        *(uint4*)(Kpk + r * KST + q4) = kw;
    }

    // ---- stage V as fp16 key-pairs ----
    const int c4 = (tid & 31) * 4;
    for (int idx = tid; idx < npad * 16; idx += 256) {
        int r2 = idx >> 5;
        int r0 = 2 * r2, r1 = r0 + 1;
        float4 va = {0,0,0,0}, vb = {0,0,0,0};
        if (r0 < n)
            va = *(const float4*)(vF + (size_t)(off + r0) * 128 + c4);
        if (r1 < n)
            vb = *(const float4*)(vF + (size_t)(off + r1) * 128 + c4);
        uint4 vp;
        vp.x = packh(va.x, vb.x);
        vp.y = packh(va.y, vb.y);
        vp.z = packh(va.z, vb.z);
        vp.w = packh(va.w, vb.w);
        *(uint4*)(Vpk + r2 * VAP + c4) = vp;
    }
    __syncthreads();

    const int warp = tid >> 5;     // head
    const int lane = tid & 31;
    const int g = lane >> 2;
    const int t = lane & 3;
    const int h16 = warp * 16;
    const int h8  = warp * 8;

    const int nmt = (n + 15) >> 4;
    const float lfix = (float)(npad - n);

    for (int mt = 0; mt < nmt; mt++) {
        const int qr0 = min(mt * 16 + g, n - 1);
        const int qr1 = min(mt * 16 + 8 + g, n - 1);
        uint2 q0 = *(const uint2*)(qP + (size_t)(off + qr0) * 64 + h8 + 2 * t);
        uint2 q1 = *(const uint2*)(qP + (size_t)(off + qr1) * 64 + h8 + 2 * t);
        uint32_t qa[4];
        qa[0] = q0.x; qa[2] = q0.y;
        qa[1] = q1.x; qa[3] = q1.y;

        float oacc[2][4];
#pragma unroll
        for (int nt = 0; nt < 2; nt++)
#pragma unroll
            for (int r = 0; r < 4; r++) oacc[nt][r] = 0.f;
        float l0 = 0.f, l1 = 0.f;

        for (int kb = 0; kb < npad; kb += 16) {
            float sA[4] = {0,0,0,0}, sB[4] = {0,0,0,0};
            const uint32_t* kA = Kpk + (kb + g) * KST + h8;
            uint2 ka2 = *(const uint2*)(kA + 2 * t);
            uint2 kb2 = *(const uint2*)(kA + 8 * KST + 2 * t);
            mma_f16(sA, qa, ka2.x, ka2.y);
            mma_f16(sB, qa, kb2.x, kb2.y);

            float pA0 = __expf(sA[0]);
            float pA1 = __expf(sA[1]);
            float pA2 = __expf(sA[2]);
            float pA3 = __expf(sA[3]);
            float pB0 = __expf(sB[0]);
            float pB1 = __expf(sB[1]);
            float pB2 = __expf(sB[2]);
            float pB3 = __expf(sB[3]);
            l0 += (pA0 + pA1) + (pB0 + pB1);
            l1 += (pA2 + pA3) + (pB2 + pB3);

            // P straight into fp16 A-fragment
            uint32_t pa[4];
            pa[0] = packh(pA0, pA1);
            pa[1] = packh(pA2, pA3);
            pa[2] = packh(pB0, pB1);
            pa[3] = packh(pB2, pB3);

#pragma unroll
            for (int nt = 0; nt < 2; nt++) {
                const uint32_t* vp = Vpk + ((kb >> 1) + t) * VAP
                                         + h16 + nt * 8 + g;
                mma_f16(oacc[nt], pa, vp[0], vp[4 * VAP]);
            }
        }

        l0 += __shfl_xor_sync(0xffffffffu, l0, 1);
        l0 += __shfl_xor_sync(0xffffffffu, l0, 2);
        l1 += __shfl_xor_sync(0xffffffffu, l1, 1);
        l1 += __shfl_xor_sync(0xffffffffu, l1, 2);
        const float inv0 = 1.f / (l0 - lfix), inv1 = 1.f / (l1 - lfix);

        const int q0r = mt * 16 + g;
        const int q1r = q0r + 8;
#pragma unroll
        for (int nt = 0; nt < 2; nt++) {
            const int wcol = h8 + nt * 4 + t;
            if (q0r < n)
                ctxP[(size_t)(off + q0r) * 64 + wcol] =
                    packh(oacc[nt][0] * inv0, oacc[nt][1] * inv0);
            if (q1r < n)
                ctxP[(size_t)(off + q1r) * 64 + wcol] =
                    packh(oacc[nt][2] * inv1, oacc[nt][3] * inv1);
        }
    }
}

// ---------------------------------------------------------------------------
extern "C" void kernel_launch(void* const* d_in, const int* in_sizes, int n_in,
                              void* d_out, int out_size)
{
    const float* att_in = (const float*)d_in[0];
    const float* w1     = (const float*)d_in[1];
    const float* b1     = (const float*)d_in[2];
    const float* w2     = (const float*)d_in[3];
    const float* b2     = (const float*)d_in[4];
    const int*   agents = (const int*)d_in[5];

    const int M  = in_sizes[0] / 128;   // 66560
    const int nB = in_sizes[5];         // 2048

    float* vF = nullptr;
    uint32_t* whp = nullptr; uint32_t* ctxP = nullptr;
    uint32_t* qP = nullptr; uint32_t* kP = nullptr;
    cudaGetSymbolAddress((void**)&ctxP, g_ctxP);
    cudaGetSymbolAddress((void**)&vF,  g_vF);
    cudaGetSymbolAddress((void**)&whp, g_whP);
    cudaGetSymbolAddress((void**)&qP,  g_qP);
    cudaGetSymbolAddress((void**)&kP,  g_kP);

    cudaFuncSetAttribute(gemm_qkv_kernel,
                         cudaFuncAttributeMaxDynamicSharedMemorySize, GEMM_SMEM);
    cudaFuncSetAttribute(gemm_out_kernel,
                         cudaFuncAttributeMaxDynamicSharedMemorySize, GEMM_SMEM);
    cudaFuncSetAttribute(attn_mma_kernel,
                         cudaFuncAttributeMaxDynamicSharedMemorySize, ATTN_SMEM);

    scan_kernel<<<1, 32>>>(agents, nB);
    wsplit_kernel<<<(W_WORDS + 255) / 256, 256>>>(w1, w2);

    gemm_qkv_kernel<<<M / 128, 256, GEMM_SMEM>>>(
        att_in, whp, b1, qP, kP, vF);

    attn_mma_kernel<<<nB, 256, ATTN_SMEM>>>(qP, kP, vF, ctxP, agents);

    gemm_out_kernel<<<M / 128, 256, GEMM_SMEM>>>(
        ctxP, whp + 384 * 64, b2, (float*)d_out);
}